// round 13
// baseline (speedup 1.0000x reference)
#include <cuda_runtime.h>
#include <cstdint>

#define BB 64
#define PP 25000
#define TT 16
#define CC 81

#define LROWS 64
#define LTILES 8
#define NTILE ((PP + LROWS - 1) / LROWS)          // 391
#define LNBX ((NTILE + LTILES - 1) / LTILES)      // 49

#define MPB 1000                                   // priors per match block (25*1000 == PP)
#define MNB 25

// ---------------- scratch ----------------
__device__ float               g_bt_ov[BB * PP];
__device__ unsigned char       g_bt_idx[BB * PP];
__device__ unsigned long long  g_bp_key[BB * TT];
__device__ float               g_loss_c[BB * PP];
__device__ int                 g_hist1[BB * 2048];
__device__ int                 g_num_pos[BB];
__device__ int                 g_total_pos;
__device__ double              g_loss_l;
__device__ double              g_ce_pos;
__device__ double              g_ce_neg;

// ---------------- async helpers ----------------
__device__ __forceinline__ unsigned smem_u32(const void* p) {
    return (unsigned)__cvta_generic_to_shared(p);
}
__device__ __forceinline__ void mbar_init(unsigned mbar, unsigned count) {
    asm volatile("mbarrier.init.shared.b64 [%0], %1;" :: "r"(mbar), "r"(count) : "memory");
}
__device__ __forceinline__ void mbar_expect_tx(unsigned mbar, unsigned bytes) {
    asm volatile("mbarrier.arrive.expect_tx.shared.b64 _, [%0], %1;"
                 :: "r"(mbar), "r"(bytes) : "memory");
}
__device__ __forceinline__ void bulk_g2s(unsigned dst, const void* src,
                                         unsigned bytes, unsigned mbar) {
    asm volatile("cp.async.bulk.shared::cluster.global.mbarrier::complete_tx::bytes "
                 "[%0], [%1], %2, [%3];"
                 :: "r"(dst), "l"(src), "r"(bytes), "r"(mbar) : "memory");
}
__device__ __forceinline__ void mbar_wait(unsigned mbar, unsigned parity) {
    asm volatile(
        "{\n\t.reg .pred P;\n\t"
        "WL%=:\n\t"
        "mbarrier.try_wait.parity.acquire.cta.shared::cta.b64 P, [%0], %1, 0x989680;\n\t"
        "@P bra.uni WD%=;\n\t"
        "bra.uni WL%=;\n\t"
        "WD%=:\n\t}"
        :: "r"(mbar), "r"(parity) : "memory");
}

// ---------------- match: register-accumulated per-truth best, no REDUX ----------------
__global__ void __launch_bounds__(256) match_kernel(const float* __restrict__ priors,
                                                    const float* __restrict__ targets) {
    const int b   = blockIdx.y;
    const int tid = threadIdx.x;
    const int p0  = blockIdx.x * MPB;
    const int lane = tid & 31;

    __shared__ float s_t[TT][4];
    __shared__ float s_ta[TT];
    __shared__ unsigned long long s_key[TT];

    if (tid < TT) {
        const float* tr = targets + ((size_t)b * TT + tid) * 5;
        float x0 = tr[0], y0 = tr[1], x1 = tr[2], y1 = tr[3];
        s_t[tid][0] = x0; s_t[tid][1] = y0;
        s_t[tid][2] = x1; s_t[tid][3] = y1;
        s_ta[tid] = (x1 - x0) * (y1 - y0);
        s_key[tid] = 0ULL;
    }
    __syncthreads();

    float bestv[TT];
    int   bestp[TT];
    #pragma unroll
    for (int t = 0; t < TT; t++) { bestv[t] = -1.0f; bestp[t] = 0; }

    for (int p = p0 + tid; p < p0 + MPB; p += 256) {     // ascending p per thread
        float4 pr = ((const float4*)priors)[p];
        float px0 = pr.x - pr.z * 0.5f, py0 = pr.y - pr.w * 0.5f;
        float px1 = pr.x + pr.z * 0.5f, py1 = pr.y + pr.w * 0.5f;
        float pa  = (px1 - px0) * (py1 - py0);

        float bov = -1.0f;
        int   bbi = 0;
        #pragma unroll
        for (int t = 0; t < TT; t++) {
            float lx = fmaxf(s_t[t][0], px0), ly = fmaxf(s_t[t][1], py0);
            float rx = fminf(s_t[t][2], px1), ry = fminf(s_t[t][3], py1);
            float iw = fmaxf(rx - lx, 0.0f), ih = fmaxf(ry - ly, 0.0f);
            float inter = iw * ih;
            float iou = inter / (s_ta[t] + pa - inter);
            if (iou > bov) { bov = iou; bbi = t; }        // strict > -> first max over t
            if (iou > bestv[t]) { bestv[t] = iou; bestp[t] = p; }  // strict > -> smallest p
        }
        g_bt_ov[(size_t)b * PP + p]  = bov;
        g_bt_idx[(size_t)b * PP + p] = (unsigned char)bbi;
    }

    // per-truth block reduction: key = (iou_bits<<32) | ~p (iou>=0 order-preserving)
    #pragma unroll
    for (int t = 0; t < TT; t++) {
        unsigned long long k =
            (((unsigned long long)__float_as_uint(bestv[t])) << 32) |
            (unsigned)(~(unsigned)bestp[t]);
        #pragma unroll
        for (int o = 16; o > 0; o >>= 1) {
            unsigned long long other = __shfl_xor_sync(0xffffffffu, k, o);
            k = (other > k) ? other : k;
        }
        if (lane == 0) atomicMax(&s_key[t], k);
    }
    __syncthreads();
    if (tid < TT) atomicMax(&g_bp_key[b * TT + tid], s_key[tid]);
}

// ---------------- fused loss (R12, unchanged): bulk-copy pipeline + inline force ----------------
__global__ void __launch_bounds__(256, 5) loss_kernel(
        const float* __restrict__ loc_data,
        const float* __restrict__ conf_data,
        const float* __restrict__ priors,
        const float* __restrict__ targets) {
    const int b   = blockIdx.y;
    const int tid = threadIdx.x;
    const int t0  = blockIdx.x * LTILES;
    const int S   = min(LTILES, NTILE - t0);

    __shared__ float s_buf[2][LROWS * CC];                 // 2 x 20736 B
    __shared__ float s_tr[TT][5];
    __shared__ int   s_bp[TT];
    __shared__ float s_ll[8], s_cep[8];
    __shared__ int   s_pos[8];
    __shared__ __align__(8) unsigned long long s_mbar[2];

    if (tid < TT * 5)
        ((float*)s_tr)[tid] = targets[(size_t)b * TT * 5 + tid];
    if (tid >= 96 && tid < 96 + TT)
        s_bp[tid - 96] = (int)(~(unsigned)(g_bp_key[b * TT + (tid - 96)] & 0xFFFFFFFFULL));

    const unsigned mb[2]  = { smem_u32(&s_mbar[0]), smem_u32(&s_mbar[1]) };
    const unsigned sb[2]  = { smem_u32(&s_buf[0][0]), smem_u32(&s_buf[1][0]) };
    if (tid == 0) { mbar_init(mb[0], 1); mbar_init(mb[1], 1); }
    __syncthreads();

    const float* cbase = conf_data + (size_t)b * PP * CC;

    if (tid == 0) {
        const int row0 = t0 * LROWS;
        const unsigned bytes = (unsigned)(min(LROWS, PP - row0) * CC * 4);
        mbar_expect_tx(mb[0], bytes);
        bulk_g2s(sb[0], cbase + (size_t)row0 * CC, bytes, mb[0]);
    }

    float my_ll = 0.f, my_cep = 0.f;
    int   my_pos = 0;

    const int strip_l = tid >> 4;
    const int h       = tid & 15;
    const int fs      = 20 * h;
    const int nf      = (h == 15) ? 6 : 5;
    const int fe      = fs + 4 * nf;
    const int splitf  = min((fs / 81 + 1) * 81, fe);
    const int r       = h >> 2;
    const bool rowlead = ((h & 3) == 0);

    for (int s = 0; s < S; s++) {
        if (s + 1 < S && tid == 0) {
            const int row0n = (t0 + s + 1) * LROWS;
            const unsigned bytes = (unsigned)(min(LROWS, PP - row0n) * CC * 4);
            mbar_expect_tx(mb[(s + 1) & 1], bytes);
            bulk_g2s(sb[(s + 1) & 1], cbase + (size_t)row0n * CC, bytes, mb[(s + 1) & 1]);
        }

        const int row0 = (t0 + s) * LROWS;
        const int rows = min(LROWS, PP - row0);
        const bool sact = (strip_l * 4 < rows);
        const int  prow = row0 + strip_l * 4 + r;

        float ovv = 0.f; int tiv = 0;
        if (rowlead && sact) {
            const size_t off = (size_t)b * PP + prow;
            ovv = g_bt_ov[off];
            tiv = g_bt_idx[off];
            #pragma unroll
            for (int j = 0; j < TT; j++)
                if (s_bp[j] == prow) { ovv = 2.0f; tiv = j; }   // last j wins
        }

        mbar_wait(mb[s & 1], (unsigned)((s >> 1) & 1));

        const float* base = s_buf[s & 1];
        float accA = 0.f, accB = 0.f;
        if (sact) {
            const float* tp = base + strip_l * 324 + fs;
            #pragma unroll
            for (int i = 0; i < 6; i++) {
                if (i < nf) {
                    float4 v = *(const float4*)(tp + 4 * i);
                    float e0 = __expf(v.x), e1 = __expf(v.y);
                    float e2 = __expf(v.z), e3 = __expf(v.w);
                    float sv = (e0 + e1) + (e2 + e3);
                    int w = fs + 4 * i;
                    if (w + 4 <= splitf)      accA += sv;
                    else if (w >= splitf)     accB += sv;
                    else {
                        accA += (w     < splitf ? e0 : 0.f) + (w + 1 < splitf ? e1 : 0.f)
                              + (w + 2 < splitf ? e2 : 0.f) + (w + 3 < splitf ? e3 : 0.f);
                        accB += (w     >= splitf ? e0 : 0.f) + (w + 1 >= splitf ? e1 : 0.f)
                              + (w + 2 >= splitf ? e2 : 0.f) + (w + 3 >= splitf ? e3 : 0.f);
                    }
                }
            }
        }

        float a1 = __shfl_down_sync(0xffffffffu, accA, 1);
        float a2 = __shfl_down_sync(0xffffffffu, accA, 2);
        float a3 = __shfl_down_sync(0xffffffffu, accA, 3);
        float a4 = __shfl_down_sync(0xffffffffu, accA, 4);
        float basev = (h == 0) ? accA : accB;
        float tot = basev + a1 + a2 + a3 + ((rowlead && r < 3) ? a4 : 0.f);

        if (rowlead && sact) {
            float lse = __logf(tot);
            bool pos = (ovv >= 0.5f);
            int  ct  = pos ? ((int)s_tr[tiv][4] + 1) : 0;
            float ce = lse - base[(strip_l * 4 + r) * 81 + ct];
            float lc = pos ? 0.f : ce;
            g_loss_c[(size_t)b * PP + prow] = lc;
            atomicAdd(&g_hist1[b * 2048 + (int)(__float_as_uint(lc) >> 21)], 1);
            if (pos) {
                my_pos++;
                my_cep += ce;
                float4 pr = ((const float4*)priors)[prow];
                float tx0 = s_tr[tiv][0], ty0 = s_tr[tiv][1];
                float tx1 = s_tr[tiv][2], ty1 = s_tr[tiv][3];
                float gx = ((tx0 + tx1) * 0.5f - pr.x) / (0.1f * pr.z);
                float gy = ((ty0 + ty1) * 0.5f - pr.y) / (0.1f * pr.w);
                float gw = __logf((tx1 - tx0) / pr.z) * 5.0f;
                float gh = __logf((ty1 - ty0) / pr.w) * 5.0f;
                float4 ld = ((const float4*)loc_data)[(size_t)b * PP + prow];
                float d, ad;
                d = ld.x - gx; ad = fabsf(d); my_ll += (ad < 1.f) ? 0.5f * d * d : ad - 0.5f;
                d = ld.y - gy; ad = fabsf(d); my_ll += (ad < 1.f) ? 0.5f * d * d : ad - 0.5f;
                d = ld.z - gw; ad = fabsf(d); my_ll += (ad < 1.f) ? 0.5f * d * d : ad - 0.5f;
                d = ld.w - gh; ad = fabsf(d); my_ll += (ad < 1.f) ? 0.5f * d * d : ad - 0.5f;
            }
        }
        __syncthreads();
    }

    #pragma unroll
    for (int o = 16; o > 0; o >>= 1) {
        my_ll  += __shfl_xor_sync(0xffffffffu, my_ll, o);
        my_cep += __shfl_xor_sync(0xffffffffu, my_cep, o);
        my_pos += __shfl_xor_sync(0xffffffffu, my_pos, o);
    }
    const int lane = tid & 31, warp = tid >> 5;
    if (lane == 0) { s_ll[warp] = my_ll; s_cep[warp] = my_cep; s_pos[warp] = my_pos; }
    __syncthreads();
    if (tid == 0) {
        float ll = 0.f, cep = 0.f; int np = 0;
        #pragma unroll
        for (int w = 0; w < 8; w++) { ll += s_ll[w]; cep += s_cep[w]; np += s_pos[w]; }
        if (np) {
            atomicAdd(&g_loss_l, (double)ll);
            atomicAdd(&g_ce_pos, (double)cep);
            atomicAdd(&g_num_pos[b], np);
            atomicAdd(&g_total_pos, np);
        }
    }
}

// ---------------- mining: register-resident, hist pass-1 + 21-bit binary select ----------------
__global__ void __launch_bounds__(1024, 1) mine_kernel() {
    const int b   = blockIdx.x;
    const int tid = threadIdx.x;
    __shared__ int      hist[2048];
    __shared__ int      s_group[64];
    __shared__ unsigned s_bin;
    __shared__ int      s_kk;
    __shared__ unsigned s_T;
    __shared__ int      s_wc[32];
    __shared__ double   s_wd[32];

    int np = g_num_pos[b];
    int k  = min(3 * np, PP - 1);
    if (k <= 0) {                               // uniform across block
        g_hist1[b * 2048 + tid] = 0;
        g_hist1[b * 2048 + 1024 + tid] = 0;
        return;
    }

    const float* lc = g_loss_c + (size_t)b * PP;

    // load all 25000 values into registers (25 per thread; j=24 partial)
    unsigned key[25];
    #pragma unroll
    for (int j = 0; j < 24; j++) key[j] = __float_as_uint(lc[tid + j * 1024]);
    const bool v24 = (tid < PP - 24 * 1024);    // tid < 424
    key[24] = v24 ? __float_as_uint(lc[tid + 24 * 1024]) : 0u;

    // pass 1: precomputed histogram (bits 31..21); reset for next replay
    hist[tid] = g_hist1[b * 2048 + tid];
    hist[tid + 1024] = g_hist1[b * 2048 + 1024 + tid];
    g_hist1[b * 2048 + tid] = 0;
    g_hist1[b * 2048 + 1024 + tid] = 0;
    __syncthreads();
    if (tid < 64) {
        int s = 0;
        #pragma unroll
        for (int j = 0; j < 32; j++) s += hist[tid * 32 + j];
        s_group[tid] = s;
    }
    __syncthreads();
    if (tid == 0) {
        int cum = 0, g = 63;
        for (; g > 0; g--) {
            if (cum + s_group[g] >= k) break;
            cum += s_group[g];
        }
        int x = g * 32 + 31;
        for (;; x--) {
            int hv = hist[x];
            if (cum + hv >= k || x == g * 32) break;
            cum += hv;
        }
        s_bin = (unsigned)x;
        s_kk  = k - cum;                         // elements needed inside the bin
    }
    __syncthreads();
    const unsigned bin = s_bin;
    const int kk = s_kk;

    // classify registers: sum above bin, mark in-bin
    const unsigned long long ubound = ((unsigned long long)(bin + 1)) << 21;
    double dsum = 0.0;
    unsigned inb = 0;
    #pragma unroll
    for (int j = 0; j < 25; j++) {
        bool val = (j < 24) || v24;
        if (val) {
            if ((unsigned long long)key[j] >= ubound)
                dsum += (double)__uint_as_float(key[j]);
            else if ((key[j] >> 21) == bin)
                inb |= (1u << j);
        }
    }

    // binary search low 21 bits for the kk-th largest key within the bin
    if (tid == 0) s_T = bin << 21;
    __syncthreads();
    for (int bit = 20; bit >= 0; bit--) {
        const unsigned T2 = s_T | (1u << bit);
        int c = 0;
        #pragma unroll
        for (int j = 0; j < 25; j++)
            c += (int)(((inb >> j) & 1u) && key[j] >= T2);
        c = __reduce_add_sync(0xffffffffu, c);
        if ((tid & 31) == 0) s_wc[tid >> 5] = c;
        __syncthreads();
        if (tid < 32) {
            int ct = __reduce_add_sync(0xffffffffu, s_wc[tid]);
            if (tid == 0 && ct >= kk) s_T = T2;
        }
        __syncthreads();
    }
    const unsigned T = s_T;

    // strictly-greater count + candidate sum
    int cgt = 0;
    #pragma unroll
    for (int j = 0; j < 25; j++) {
        if (((inb >> j) & 1u) && key[j] > T) {
            cgt++;
            dsum += (double)__uint_as_float(key[j]);
        }
    }
    cgt = __reduce_add_sync(0xffffffffu, cgt);
    #pragma unroll
    for (int o = 16; o > 0; o >>= 1) dsum += __shfl_xor_sync(0xffffffffu, dsum, o);
    const int lane = tid & 31, w = tid >> 5;
    if (lane == 0) { s_wc[w] = cgt; s_wd[w] = dsum; }
    __syncthreads();
    if (tid == 0) {
        int totgt = 0; double tot = 0.0;
        #pragma unroll
        for (int i = 0; i < 32; i++) { totgt += s_wc[i]; tot += s_wd[i]; }
        tot += (double)(kk - totgt) * (double)__uint_as_float(T);
        atomicAdd(&g_ce_neg, tot);
    }
}

// ---------------- finalize + remaining cleanup (1 block) ----------------
__global__ void final_kernel(float* out) {
    const int tid = threadIdx.x;
    if (tid == 0) {
        double N = (double)g_total_pos;
        if (N < 1.0) N = 1.0;
        out[0] = (float)(g_loss_l / N);
        out[1] = (float)((g_ce_pos + g_ce_neg) / N);
        g_total_pos = 0; g_loss_l = 0.0; g_ce_pos = 0.0; g_ce_neg = 0.0;
    }
    g_bp_key[tid] = 0ULL;                       // BB*TT == 1024
    if (tid < BB) g_num_pos[tid] = 0;
}

extern "C" void kernel_launch(void* const* d_in, const int* in_sizes, int n_in,
                              void* d_out, int out_size) {
    const float* loc_data  = (const float*)d_in[0];   // [B,P,4]
    const float* conf_data = (const float*)d_in[1];   // [B,P,81]
    const float* priors    = (const float*)d_in[2];   // [P,4]
    const float* targets   = (const float*)d_in[3];   // [B,T,5]
    float* out = (float*)d_out;

    match_kernel<<<dim3(MNB, BB), 256>>>(priors, targets);
    loss_kernel<<<dim3(LNBX, BB), 256>>>(loc_data, conf_data, priors, targets);
    mine_kernel<<<BB, 1024>>>();
    final_kernel<<<1, 1024>>>(out);
}

// round 14
// speedup vs baseline: 1.5317x; 1.5317x over previous
#include <cuda_runtime.h>
#include <cstdint>

#define BB 64
#define PP 25000
#define TT 16
#define CC 81

#define LROWS 64
#define LTILES 8
#define NTILE ((PP + LROWS - 1) / LROWS)          // 391
#define LNBX ((NTILE + LTILES - 1) / LTILES)      // 49

// ---------------- scratch ----------------
__device__ float               g_bt_ov[BB * PP];
__device__ unsigned char       g_bt_idx[BB * PP];
__device__ unsigned long long  g_bp_key[BB * TT];
__device__ float               g_loss_c[BB * PP];
__device__ int                 g_hist1[BB * 2048];
__device__ int                 g_num_pos[BB];
__device__ int                 g_total_pos;
__device__ int                 g_ticket;
__device__ double              g_loss_l;
__device__ double              g_ce_pos;
__device__ double              g_ce_neg;

// ---------------- async helpers ----------------
__device__ __forceinline__ unsigned smem_u32(const void* p) {
    return (unsigned)__cvta_generic_to_shared(p);
}
__device__ __forceinline__ void mbar_init(unsigned mbar, unsigned count) {
    asm volatile("mbarrier.init.shared.b64 [%0], %1;" :: "r"(mbar), "r"(count) : "memory");
}
__device__ __forceinline__ void mbar_expect_tx(unsigned mbar, unsigned bytes) {
    asm volatile("mbarrier.arrive.expect_tx.shared.b64 _, [%0], %1;"
                 :: "r"(mbar), "r"(bytes) : "memory");
}
__device__ __forceinline__ void bulk_g2s(unsigned dst, const void* src,
                                         unsigned bytes, unsigned mbar) {
    asm volatile("cp.async.bulk.shared::cluster.global.mbarrier::complete_tx::bytes "
                 "[%0], [%1], %2, [%3];"
                 :: "r"(dst), "l"(src), "r"(bytes), "r"(mbar) : "memory");
}
__device__ __forceinline__ void mbar_wait(unsigned mbar, unsigned parity) {
    asm volatile(
        "{\n\t.reg .pred P;\n\t"
        "WL%=:\n\t"
        "mbarrier.try_wait.parity.acquire.cta.shared::cta.b64 P, [%0], %1, 0x989680;\n\t"
        "@P bra.uni WD%=;\n\t"
        "bra.uni WL%=;\n\t"
        "WD%=:\n\t}"
        :: "r"(mbar), "r"(parity) : "memory");
}

// ---------------- match (R9): REDUX per-prior + per-truth ----------------
__global__ void match_kernel(const float* __restrict__ priors,
                             const float* __restrict__ targets) {
    const int b = blockIdx.y;
    const int p = blockIdx.x * 256 + threadIdx.x;
    const int lane = threadIdx.x & 31;
    __shared__ float s_t[TT][4];
    __shared__ float s_ta[TT];
    __shared__ unsigned long long s_key[TT];

    if (threadIdx.x < TT) {
        const float* tr = targets + ((size_t)b * TT + threadIdx.x) * 5;
        float x0 = tr[0], y0 = tr[1], x1 = tr[2], y1 = tr[3];
        s_t[threadIdx.x][0] = x0; s_t[threadIdx.x][1] = y0;
        s_t[threadIdx.x][2] = x1; s_t[threadIdx.x][3] = y1;
        s_ta[threadIdx.x] = (x1 - x0) * (y1 - y0);
        s_key[threadIdx.x] = 0ULL;
    }
    __syncthreads();

    const bool valid = (p < PP);
    float px0 = 0.f, py0 = 0.f, px1 = 0.f, py1 = 0.f, pa = 0.f;
    if (valid) {
        float4 pr = ((const float4*)priors)[p];
        px0 = pr.x - pr.z * 0.5f; py0 = pr.y - pr.w * 0.5f;
        px1 = pr.x + pr.z * 0.5f; py1 = pr.y + pr.w * 0.5f;
        pa  = (px1 - px0) * (py1 - py0);
    }

    float best = -1.0f;
    int   bi   = 0;

    #pragma unroll
    for (int t = 0; t < TT; t++) {
        unsigned ib = 0;
        if (valid) {
            float lx = fmaxf(s_t[t][0], px0), ly = fmaxf(s_t[t][1], py0);
            float rx = fminf(s_t[t][2], px1), ry = fminf(s_t[t][3], py1);
            float iw = fmaxf(rx - lx, 0.0f), ih = fmaxf(ry - ly, 0.0f);
            float inter = iw * ih;
            float iou = inter / (s_ta[t] + pa - inter);
            if (iou > best) { best = iou; bi = t; }           // strict > -> first max
            ib = __float_as_uint(iou);                        // iou >= 0 -> order-preserving
        }
        unsigned wmax = __reduce_max_sync(0xffffffffu, ib);
        unsigned cp   = (valid && ib == wmax) ? (unsigned)p : 0xFFFFFFFFu;
        unsigned pmin = __reduce_min_sync(0xffffffffu, cp);   // tie -> smallest p
        if (lane == 0) {
            unsigned long long key = (((unsigned long long)wmax) << 32) | (unsigned)(~pmin);
            atomicMax(&s_key[t], key);
        }
    }

    if (valid) {
        g_bt_ov[(size_t)b * PP + p]  = best;
        g_bt_idx[(size_t)b * PP + p] = (unsigned char)bi;
    }
    __syncthreads();
    if (threadIdx.x < TT) atomicMax(&g_bp_key[b * TT + threadIdx.x], s_key[threadIdx.x]);
}

// ---------------- force each truth's best prior (last j wins) ----------------
__global__ void force_kernel() {
    int b = threadIdx.x;
    if (b >= BB) return;
    for (int j = 0; j < TT; j++) {
        unsigned long long key = g_bp_key[b * TT + j];
        unsigned p = ~(unsigned)(key & 0xFFFFFFFFULL);
        g_bt_ov[(size_t)b * PP + p]  = 2.0f;
        g_bt_idx[(size_t)b * PP + p] = (unsigned char)j;
    }
}

// ---------------- fused loss (R9): bulk-copy double buffer + shuffle combine ----------------
__global__ void __launch_bounds__(256, 5) loss_kernel(
        const float* __restrict__ loc_data,
        const float* __restrict__ conf_data,
        const float* __restrict__ priors,
        const float* __restrict__ targets) {
    const int b   = blockIdx.y;
    const int tid = threadIdx.x;
    const int t0  = blockIdx.x * LTILES;
    const int S   = min(LTILES, NTILE - t0);

    __shared__ float s_buf[2][LROWS * CC];                 // 2 x 20736 B
    __shared__ float s_tr[TT][5];
    __shared__ float s_ll[8], s_cep[8];
    __shared__ int   s_pos[8];
    __shared__ __align__(8) unsigned long long s_mbar[2];

    if (tid < TT * 5)
        ((float*)s_tr)[tid] = targets[(size_t)b * TT * 5 + tid];

    const unsigned mb[2]  = { smem_u32(&s_mbar[0]), smem_u32(&s_mbar[1]) };
    const unsigned sb[2]  = { smem_u32(&s_buf[0][0]), smem_u32(&s_buf[1][0]) };
    if (tid == 0) { mbar_init(mb[0], 1); mbar_init(mb[1], 1); }
    __syncthreads();

    const float* cbase = conf_data + (size_t)b * PP * CC;

    if (tid == 0) {
        const int row0 = t0 * LROWS;
        const unsigned bytes = (unsigned)(min(LROWS, PP - row0) * CC * 4);
        mbar_expect_tx(mb[0], bytes);
        bulk_g2s(sb[0], cbase + (size_t)row0 * CC, bytes, mb[0]);
    }

    float my_ll = 0.f, my_cep = 0.f;
    int   my_pos = 0;

    const int strip_l = tid >> 4;
    const int h       = tid & 15;
    const int fs      = 20 * h;
    const int nf      = (h == 15) ? 6 : 5;
    const int fe      = fs + 4 * nf;
    const int splitf  = min((fs / 81 + 1) * 81, fe);
    const int r       = h >> 2;
    const bool rowlead = ((h & 3) == 0);

    for (int s = 0; s < S; s++) {
        if (s + 1 < S && tid == 0) {
            const int row0n = (t0 + s + 1) * LROWS;
            const unsigned bytes = (unsigned)(min(LROWS, PP - row0n) * CC * 4);
            mbar_expect_tx(mb[(s + 1) & 1], bytes);
            bulk_g2s(sb[(s + 1) & 1], cbase + (size_t)row0n * CC, bytes, mb[(s + 1) & 1]);
        }

        const int row0 = (t0 + s) * LROWS;
        const int rows = min(LROWS, PP - row0);
        const bool sact = (strip_l * 4 < rows);
        const int  prow = row0 + strip_l * 4 + r;

        float ovv = 0.f; int tiv = 0;
        if (rowlead && sact) {
            const size_t off = (size_t)b * PP + prow;
            ovv = g_bt_ov[off];
            tiv = g_bt_idx[off];
        }

        mbar_wait(mb[s & 1], (unsigned)((s >> 1) & 1));

        const float* base = s_buf[s & 1];
        float accA = 0.f, accB = 0.f;
        if (sact) {
            const float* tp = base + strip_l * 324 + fs;
            #pragma unroll
            for (int i = 0; i < 6; i++) {
                if (i < nf) {
                    float4 v = *(const float4*)(tp + 4 * i);
                    float e0 = __expf(v.x), e1 = __expf(v.y);
                    float e2 = __expf(v.z), e3 = __expf(v.w);
                    float sv = (e0 + e1) + (e2 + e3);
                    int w = fs + 4 * i;
                    if (w + 4 <= splitf)      accA += sv;
                    else if (w >= splitf)     accB += sv;
                    else {
                        accA += (w     < splitf ? e0 : 0.f) + (w + 1 < splitf ? e1 : 0.f)
                              + (w + 2 < splitf ? e2 : 0.f) + (w + 3 < splitf ? e3 : 0.f);
                        accB += (w     >= splitf ? e0 : 0.f) + (w + 1 >= splitf ? e1 : 0.f)
                              + (w + 2 >= splitf ? e2 : 0.f) + (w + 3 >= splitf ? e3 : 0.f);
                    }
                }
            }
        }

        float a1 = __shfl_down_sync(0xffffffffu, accA, 1);
        float a2 = __shfl_down_sync(0xffffffffu, accA, 2);
        float a3 = __shfl_down_sync(0xffffffffu, accA, 3);
        float a4 = __shfl_down_sync(0xffffffffu, accA, 4);
        float basev = (h == 0) ? accA : accB;
        float tot = basev + a1 + a2 + a3 + ((rowlead && r < 3) ? a4 : 0.f);

        if (rowlead && sact) {
            float lse = __logf(tot);
            bool pos = (ovv >= 0.5f);
            int  ct  = pos ? ((int)s_tr[tiv][4] + 1) : 0;
            float ce = lse - base[(strip_l * 4 + r) * 81 + ct];
            float lc = pos ? 0.f : ce;
            g_loss_c[(size_t)b * PP + prow] = lc;
            atomicAdd(&g_hist1[b * 2048 + (int)(__float_as_uint(lc) >> 21)], 1);
            if (pos) {
                my_pos++;
                my_cep += ce;
                float4 pr = ((const float4*)priors)[prow];
                float tx0 = s_tr[tiv][0], ty0 = s_tr[tiv][1];
                float tx1 = s_tr[tiv][2], ty1 = s_tr[tiv][3];
                float gx = ((tx0 + tx1) * 0.5f - pr.x) / (0.1f * pr.z);
                float gy = ((ty0 + ty1) * 0.5f - pr.y) / (0.1f * pr.w);
                float gw = __logf((tx1 - tx0) / pr.z) * 5.0f;
                float gh = __logf((ty1 - ty0) / pr.w) * 5.0f;
                float4 ld = ((const float4*)loc_data)[(size_t)b * PP + prow];
                float d, ad;
                d = ld.x - gx; ad = fabsf(d); my_ll += (ad < 1.f) ? 0.5f * d * d : ad - 0.5f;
                d = ld.y - gy; ad = fabsf(d); my_ll += (ad < 1.f) ? 0.5f * d * d : ad - 0.5f;
                d = ld.z - gw; ad = fabsf(d); my_ll += (ad < 1.f) ? 0.5f * d * d : ad - 0.5f;
                d = ld.w - gh; ad = fabsf(d); my_ll += (ad < 1.f) ? 0.5f * d * d : ad - 0.5f;
            }
        }
        __syncthreads();
    }

    #pragma unroll
    for (int o = 16; o > 0; o >>= 1) {
        my_ll  += __shfl_xor_sync(0xffffffffu, my_ll, o);
        my_cep += __shfl_xor_sync(0xffffffffu, my_cep, o);
        my_pos += __shfl_xor_sync(0xffffffffu, my_pos, o);
    }
    const int lane = tid & 31, warp = tid >> 5;
    if (lane == 0) { s_ll[warp] = my_ll; s_cep[warp] = my_cep; s_pos[warp] = my_pos; }
    __syncthreads();
    if (tid == 0) {
        float ll = 0.f, cep = 0.f; int np = 0;
        #pragma unroll
        for (int w = 0; w < 8; w++) { ll += s_ll[w]; cep += s_cep[w]; np += s_pos[w]; }
        if (np) {
            atomicAdd(&g_loss_l, (double)ll);
            atomicAdd(&g_ce_pos, (double)cep);
            atomicAdd(&g_num_pos[b], np);
            atomicAdd(&g_total_pos, np);
        }
    }
}

// ---------------- mining (R9) + merged finalize via last-block ticket ----------------
__global__ void mine_kernel(float* __restrict__ out) {
    const int b   = blockIdx.x;
    const int tid = threadIdx.x;
    __shared__ int      hist[2048];
    __shared__ int      s_group[64];
    __shared__ unsigned s_prefix;
    __shared__ int      s_kk;
    __shared__ int      s_last;

    int np = g_num_pos[b];
    int k  = min(3 * np, PP - 1);

    if (k > 0) {
        const float* lc = g_loss_c + (size_t)b * PP;
        unsigned prefix = 0;
        int kk = k;

        // pass 1: precomputed histogram (bits 31..21); reset for next replay
        hist[tid] = g_hist1[b * 2048 + tid];
        hist[tid + 1024] = g_hist1[b * 2048 + 1024 + tid];
        g_hist1[b * 2048 + tid] = 0;
        g_hist1[b * 2048 + 1024 + tid] = 0;
        __syncthreads();
        {
            if (tid < 64) {
                int s = 0;
                #pragma unroll
                for (int j = 0; j < 32; j++) s += hist[tid * 32 + j];
                s_group[tid] = s;
            }
            __syncthreads();
            if (tid == 0) {
                int cum = 0, g = 63;
                for (; g > 0; g--) {
                    if (cum + s_group[g] >= kk) break;
                    cum += s_group[g];
                }
                int x = g * 32 + 31;
                for (;; x--) {
                    int hv = hist[x];
                    if (cum + hv >= kk || x == g * 32) break;
                    cum += hv;
                }
                s_prefix = ((unsigned)x << 21);
                s_kk = kk - cum;
            }
            __syncthreads();
            prefix = s_prefix;
            kk     = s_kk;
        }

        // passes 2 & 3 (global, 8-unrolled)
        const int shifts[2] = {10, 0};
        const int nbits [2] = {11, 10};
        #pragma unroll
        for (int pass = 0; pass < 2; pass++) {
            const int shift = shifts[pass];
            const int nb    = 1 << nbits[pass];
            hist[tid] = 0; hist[tid + 1024] = 0;
            __syncthreads();
            const unsigned hmask = 0xFFFFFFFFu << (shift + nbits[pass]);
            const unsigned bmask = (unsigned)(nb - 1);

            int i = tid;
            for (; i + 7 * 1024 < PP; i += 8 * 1024) {
                unsigned kx[8];
                #pragma unroll
                for (int u = 0; u < 8; u++) kx[u] = __float_as_uint(lc[i + u * 1024]);
                #pragma unroll
                for (int u = 0; u < 8; u++)
                    if ((kx[u] & hmask) == prefix) atomicAdd(&hist[(kx[u] >> shift) & bmask], 1);
            }
            for (; i < PP; i += 1024) {
                unsigned key = __float_as_uint(lc[i]);
                if ((key & hmask) == prefix) atomicAdd(&hist[(key >> shift) & bmask], 1);
            }
            __syncthreads();

            const int ngroups = nb >> 5;
            if (tid < ngroups) {
                int s = 0;
                #pragma unroll
                for (int j = 0; j < 32; j++) s += hist[tid * 32 + j];
                s_group[tid] = s;
            }
            __syncthreads();
            if (tid == 0) {
                int cum = 0, g = ngroups - 1;
                for (; g > 0; g--) {
                    if (cum + s_group[g] >= kk) break;
                    cum += s_group[g];
                }
                int x = g * 32 + 31;
                for (;; x--) {
                    int hv = hist[x];
                    if (cum + hv >= kk || x == g * 32) break;
                    cum += hv;
                }
                s_prefix = prefix | ((unsigned)x << shift);
                s_kk = kk - cum;
            }
            __syncthreads();
            prefix = s_prefix;
            kk     = s_kk;
        }

        float  thr   = __uint_as_float(prefix);
        double local = 0.0;
        {
            int i = tid;
            for (; i + 7 * 1024 < PP; i += 8 * 1024) {
                float a[8];
                #pragma unroll
                for (int u = 0; u < 8; u++) a[u] = lc[i + u * 1024];
                #pragma unroll
                for (int u = 0; u < 8; u++)
                    if (__float_as_uint(a[u]) > prefix) local += (double)a[u];
            }
            for (; i < PP; i += 1024) {
                float v = lc[i];
                if (__float_as_uint(v) > prefix) local += (double)v;
            }
        }
        #pragma unroll
        for (int o = 16; o > 0; o >>= 1) local += __shfl_xor_sync(0xffffffffu, local, o);
        __shared__ double sdl[32];
        int lane = tid & 31, w = tid >> 5;
        if (lane == 0) sdl[w] = local;
        __syncthreads();
        if (tid == 0) {
            double tot = 0.0;
            for (int i = 0; i < 32; i++) tot += sdl[i];
            tot += (double)kk * (double)thr;
            atomicAdd(&g_ce_neg, tot);
        }
    } else {
        // still reset this batch's histogram for the next replay
        g_hist1[b * 2048 + tid] = 0;
        g_hist1[b * 2048 + 1024 + tid] = 0;
    }

    // ---- last-block finalize + state reset (replaces final_kernel) ----
    __syncthreads();
    if (tid == 0) {
        __threadfence();
        s_last = (atomicAdd(&g_ticket, 1) == BB - 1) ? 1 : 0;
    }
    __syncthreads();
    if (s_last) {
        if (tid == 0) {
            double N = (double)g_total_pos;
            if (N < 1.0) N = 1.0;
            out[0] = (float)(g_loss_l / N);
            out[1] = (float)((g_ce_pos + g_ce_neg) / N);
            g_total_pos = 0; g_loss_l = 0.0; g_ce_pos = 0.0; g_ce_neg = 0.0;
            g_ticket = 0;
        }
        g_bp_key[tid] = 0ULL;                   // BB*TT == 1024
        if (tid < BB) g_num_pos[tid] = 0;
    }
}

extern "C" void kernel_launch(void* const* d_in, const int* in_sizes, int n_in,
                              void* d_out, int out_size) {
    const float* loc_data  = (const float*)d_in[0];   // [B,P,4]
    const float* conf_data = (const float*)d_in[1];   // [B,P,81]
    const float* priors    = (const float*)d_in[2];   // [P,4]
    const float* targets   = (const float*)d_in[3];   // [B,T,5]
    float* out = (float*)d_out;

    match_kernel<<<dim3((PP + 255) / 256, BB), 256>>>(priors, targets);
    force_kernel<<<1, BB>>>();
    loss_kernel<<<dim3(LNBX, BB), 256>>>(loc_data, conf_data, priors, targets);
    mine_kernel<<<BB, 1024>>>(out);
}